// round 6
// baseline (speedup 1.0000x reference)
#include <cuda_runtime.h>
#include <cstdint>

// Problem constants (dataset-fixed; guards use runtime sizes)
#define HDIM 64
#define KD1 128   // 2H
#define C1 256    // 4H
#define C2 64     // H
#define NMAX 65536
#define EMAXN 1048576

// Scratch (static __device__ arrays -- allocation-free rule)
__device__ float g_P[(size_t)NMAX * C1];      // emb @ W1_top   [n][c]  (folded in-place)
__device__ float g_Q[(size_t)NMAX * C1];      // emb @ W1_bot   [n][c]  (folded in-place)
__device__ float g_h2[(size_t)EMAXN * C2];    // layer-2 pre-norm [e][c]
__device__ int   g_col[EMAXN], g_row[EMAXN];  // canonical int32 indices
__device__ int   g_idx64;                     // 1 if edge_index is int64
__device__ float g_sum1[C1], g_ssq1[C1], g_mean1[C1], g_rstd1[C1];
__device__ float g_sum2[C2], g_ssq2[C2], g_mean2[C2], g_rstd2[C2];

// ---------- f32x2 packed-FMA helpers (FFMA2; only reachable via PTX) ----------
__device__ __forceinline__ unsigned long long pack2(float lo, float hi) {
    unsigned long long r;
    asm("mov.b64 %0, {%1, %2};" : "=l"(r) : "f"(lo), "f"(hi));
    return r;
}
__device__ __forceinline__ void fma2(unsigned long long& d, unsigned long long a,
                                     unsigned long long b) {
    asm("fma.rn.f32x2 %0, %1, %2, %0;" : "+l"(d) : "l"(a), "l"(b));
}
__device__ __forceinline__ float2 unpack2(unsigned long long v) {
    float lo, hi;
    asm("mov.b64 {%0, %1}, %2;" : "=f"(lo), "=f"(hi) : "l"(v));
    return make_float2(lo, hi);
}

// ---------- K-1: sniff edge_index dtype (int32 vs int64) ----------
// Reads only the first min(16,E) 8-byte slots: in-bounds under BOTH
// interpretations (int32 buffer has 2E*4 = E*8 bytes).
__global__ void k_sniff(const void* eidx, int E, int N) {
    if (threadIdx.x == 0 && blockIdx.x == 0) {
        const long long* p64 = (const long long*)eidx;
        int n = E < 16 ? E : 16;
        int ok = 1;
        for (int i = 0; i < n; i++) {
            long long v = p64[i];
            if (v < 0 || v >= (long long)N) ok = 0;
        }
        g_idx64 = ok;
    }
}

// ---------- K0a: convert indices to canonical int32 ----------
__global__ void __launch_bounds__(256) k_cvt(const void* eidx, int E) {
    const int is64 = g_idx64;
    const int stride = gridDim.x * 256;
    if (is64) {
        const long long* p = (const long long*)eidx;
        for (int e = blockIdx.x * 256 + threadIdx.x; e < E; e += stride) {
            g_col[e] = (int)p[e];
            g_row[e] = (int)p[E + e];
        }
    } else {
        const int* p = (const int*)eidx;
        for (int e = blockIdx.x * 256 + threadIdx.x; e < E; e += stride) {
            g_col[e] = p[e];
            g_row[e] = p[E + e];
        }
    }
}

__global__ void k_zero_stats() {
    int t = threadIdx.x;
    if (t < C1) { g_sum1[t] = 0.f; g_ssq1[t] = 0.f; }
    if (t < C2) { g_sum2[t] = 0.f; g_ssq2[t] = 0.f; }
}

// ---------- K1: node-level pre-GEMM  P = emb@W1_top, Q = emb@W1_bot ----------
// 256 threads: eg=tid>>5 (8 groups x 4 nodes = 32 nodes/chunk), cg=tid&31.
#define SMEMP_BYTES (64 * 512 * 4 + 32 * 64 * 8)   // 147456

__global__ void __launch_bounds__(256, 1) k_pre(
    const float* __restrict__ emb, const float* __restrict__ W1, int N)
{
    extern __shared__ float smem[];
    float* ws = smem;                                                  // [64][512]
    unsigned long long* xsd = (unsigned long long*)(smem + 64 * 512);  // [32][64] dup

    const int tid = threadIdx.x;
    // Stage W' : row k = [W1[k][0..255] | W1[64+k][0..255]]
    {
        const float4* w4 = (const float4*)W1;
        float4* ws4 = (float4*)ws;
        #pragma unroll 8
        for (int i = tid; i < 64 * 128; i += 256) {
            int k = i >> 7, c4 = i & 127;
            ws4[i] = (c4 < 64) ? w4[k * 64 + c4] : w4[4096 + k * 64 + (c4 - 64)];
        }
    }

    const int eg = tid >> 5;
    const int cg = tid & 31;
    const int c0 = cg * 4;
    const int nchunk = (N + 31) >> 5;

    for (int ch = blockIdx.x; ch < nchunk; ch += gridDim.x) {
        const int base = ch << 5;
        __syncthreads();
        #pragma unroll 2
        for (int i = tid; i < 512; i += 256) {
            int n = i >> 4, k4 = i & 15;
            float4 v = make_float4(0.f, 0.f, 0.f, 0.f);
            if (base + n < N)
                v = ((const float4*)emb)[(size_t)(base + n) * 16 + k4];
            ulonglong2* d = (ulonglong2*)(xsd + n * 64 + k4 * 4);
            d[0] = make_ulonglong2(pack2(v.x, v.x), pack2(v.y, v.y));
            d[1] = make_ulonglong2(pack2(v.z, v.z), pack2(v.w, v.w));
        }
        __syncthreads();

        unsigned long long acc[4][4][2];  // [node][h-group][pair]
        #pragma unroll
        for (int j = 0; j < 4; j++)
            #pragma unroll
            for (int h = 0; h < 4; h++) { acc[j][h][0] = 0ull; acc[j][h][1] = 0ull; }

        const unsigned long long* xrow = xsd + (eg * 4) * 64;
        #pragma unroll 2
        for (int k = 0; k < 64; k++) {
            ulonglong2 w0  = *(const ulonglong2*)(ws + k * 512 +   0 + c0);
            ulonglong2 w1v = *(const ulonglong2*)(ws + k * 512 + 128 + c0);
            ulonglong2 w2v = *(const ulonglong2*)(ws + k * 512 + 256 + c0);
            ulonglong2 w3v = *(const ulonglong2*)(ws + k * 512 + 384 + c0);
            #pragma unroll
            for (int j = 0; j < 4; j++) {
                unsigned long long xx = xrow[j * 64 + k];
                fma2(acc[j][0][0], w0.x, xx);  fma2(acc[j][0][1], w0.y, xx);
                fma2(acc[j][1][0], w1v.x, xx); fma2(acc[j][1][1], w1v.y, xx);
                fma2(acc[j][2][0], w2v.x, xx); fma2(acc[j][2][1], w2v.y, xx);
                fma2(acc[j][3][0], w3v.x, xx); fma2(acc[j][3][1], w3v.y, xx);
            }
        }

        #pragma unroll
        for (int j = 0; j < 4; j++) {
            int n = base + eg * 4 + j;
            if (n < N) {
                #pragma unroll
                for (int h = 0; h < 4; h++) {
                    float2 a  = unpack2(acc[j][h][0]);
                    float2 bq = unpack2(acc[j][h][1]);
                    float4 v = make_float4(a.x, a.y, bq.x, bq.y);
                    if (h < 2)
                        *(float4*)&g_P[(size_t)n * C1 + h * 128 + c0] = v;
                    else
                        *(float4*)&g_Q[(size_t)n * C1 + (h - 2) * 128 + c0] = v;
                }
            }
        }
    }
}

// ---------- K2: layer-1 stats over h1 = P[col]+Q[row]+b1 (never materialized) ----------
__global__ void __launch_bounds__(256) k_stats1(const float* __restrict__ b1, int E)
{
    __shared__ float bsum[C1], bssq[C1];
    const int tid = threadIdx.x;
    const int lane = tid & 31, wid = tid >> 5;
    const int c0 = lane * 8;
    if (tid < C1) { bsum[tid] = 0.f; bssq[tid] = 0.f; }
    __syncthreads();

    float bb[8];
    #pragma unroll
    for (int i = 0; i < 8; i++) bb[i] = b1[c0 + i];
    float lsum[8], lssq[8];
    #pragma unroll
    for (int i = 0; i < 8; i++) { lsum[i] = 0.f; lssq[i] = 0.f; }

    const int stride = gridDim.x * 8;
    for (int e = blockIdx.x * 8 + wid; e < E; e += stride) {
        int col = g_col[e];
        int row = g_row[e];
        const float4* pp = (const float4*)(g_P + (size_t)col * C1 + c0);
        const float4* qq = (const float4*)(g_Q + (size_t)row * C1 + c0);
        float4 p0 = pp[0], p1 = pp[1];
        float4 q0 = qq[0], q1 = qq[1];
        float h;
        h = p0.x + q0.x + bb[0]; lsum[0] += h; lssq[0] += h * h;
        h = p0.y + q0.y + bb[1]; lsum[1] += h; lssq[1] += h * h;
        h = p0.z + q0.z + bb[2]; lsum[2] += h; lssq[2] += h * h;
        h = p0.w + q0.w + bb[3]; lsum[3] += h; lssq[3] += h * h;
        h = p1.x + q1.x + bb[4]; lsum[4] += h; lssq[4] += h * h;
        h = p1.y + q1.y + bb[5]; lsum[5] += h; lssq[5] += h * h;
        h = p1.z + q1.z + bb[6]; lsum[6] += h; lssq[6] += h * h;
        h = p1.w + q1.w + bb[7]; lsum[7] += h; lssq[7] += h * h;
    }
    #pragma unroll
    for (int i = 0; i < 8; i++) {
        atomicAdd(&bsum[c0 + i], lsum[i]);
        atomicAdd(&bssq[c0 + i], lssq[i]);
    }
    __syncthreads();
    if (tid < C1) {
        atomicAdd(&g_sum1[tid], bsum[tid]);
        atomicAdd(&g_ssq1[tid], bssq[tid]);
    }
}

// ---------- K3: finalize layer-1 stats ----------
__global__ void k_fin1(float invE) {
    int c = threadIdx.x; // 256
    float m = g_sum1[c] * invE;
    float v = g_ssq1[c] * invE - m * m;
    g_mean1[c] = m;
    g_rstd1[c] = rsqrtf(v + 1e-5f);
}

// ---------- K3b: fold norm affine into P/Q (in place) ----------
// P' = P * r1 ; Q' = (Q + b1 - m1) * r1   ->  h1norm = P'[col] + Q'[row]
__global__ void __launch_bounds__(256) k_fold(const float* __restrict__ b1, int N)
{
    __shared__ float sr[C1], sq[C1];  // r1[c], (b1-m1)*r1[c]
    const int tid = threadIdx.x;
    if (tid < C1) {
        float r = g_rstd1[tid];
        sr[tid] = r;
        sq[tid] = (b1[tid] - g_mean1[tid]) * r;
    }
    __syncthreads();
    const size_t total = (size_t)N * (C1 / 4);
    for (size_t i = (size_t)blockIdx.x * 256 + tid; i < total; i += (size_t)gridDim.x * 256) {
        int c = ((int)(i & 63)) * 4;
        float4 p = ((float4*)g_P)[i];
        float4 q = ((float4*)g_Q)[i];
        p.x *= sr[c + 0]; p.y *= sr[c + 1]; p.z *= sr[c + 2]; p.w *= sr[c + 3];
        q.x = q.x * sr[c + 0] + sq[c + 0];
        q.y = q.y * sr[c + 1] + sq[c + 1];
        q.z = q.z * sr[c + 2] + sq[c + 2];
        q.w = q.w * sr[c + 3] + sq[c + 3];
        ((float4*)g_P)[i] = p;
        ((float4*)g_Q)[i] = q;
    }
}

// ---------- K4: fused relu(P'+Q') -> GEMM2 -> g_h2 + stats2 ----------
// 256 threads. eg=tid>>4 (16 groups x 8 edges = 128 edges/chunk), cg=tid&15 -> 4 ch.
#define SMEM2_FLOATS (C1 * C2 + C1 * 132)
#define SMEM2_BYTES  (SMEM2_FLOATS * 4)   // 200704

__global__ void __launch_bounds__(256, 1) k_gemm2f(
    const float* __restrict__ W2, const float* __restrict__ b2, int E)
{
    extern __shared__ float smem[];
    float* ws = smem;               // [256][64]
    float* xs = ws + C1 * C2;       // [256][132] k-major, pad -> conflict-free

    __shared__ float bsum2[C2], bssq2[C2];

    const int tid = threadIdx.x;
    {
        const float4* w4 = (const float4*)W2;
        float4* ws4 = (float4*)ws;
        #pragma unroll 8
        for (int i = tid; i < C1 * C2 / 4; i += 256) ws4[i] = w4[i];
        if (tid < C2) { bsum2[tid] = 0.f; bssq2[tid] = 0.f; }
    }

    const int cg = tid & 15;
    const int eg = tid >> 4;          // 0..15
    const int c0 = cg * 4;
    const int es = tid & 127;         // staging edge slot
    const int chalf = (tid >> 7) * 128;

    float bb[4];
    #pragma unroll
    for (int i = 0; i < 4; i++) bb[i] = b2[c0 + i];

    float lsum[4], lssq[4];
    #pragma unroll
    for (int i = 0; i < 4; i++) { lsum[i] = 0.f; lssq[i] = 0.f; }

    const int nchunk = (E + 127) >> 7;

    for (int ch = blockIdx.x; ch < nchunk; ch += gridDim.x) {
        const int base = ch << 7;
        __syncthreads();
        // Stage: relu(P'[col] + Q'[row]) -> xs[k][e]
        const int ge = base + es;
        if (ge < E) {
            int col = g_col[ge];
            int row = g_row[ge];
            const float4* pp = (const float4*)(g_P + (size_t)col * C1 + chalf);
            const float4* qq = (const float4*)(g_Q + (size_t)row * C1 + chalf);
            #pragma unroll 8
            for (int c4 = 0; c4 < 32; c4++) {
                float4 p = pp[c4], q = qq[c4];
                int c = chalf + c4 * 4;
                xs[(c + 0) * 132 + es] = fmaxf(p.x + q.x, 0.f);
                xs[(c + 1) * 132 + es] = fmaxf(p.y + q.y, 0.f);
                xs[(c + 2) * 132 + es] = fmaxf(p.z + q.z, 0.f);
                xs[(c + 3) * 132 + es] = fmaxf(p.w + q.w, 0.f);
            }
        } else {
            #pragma unroll 8
            for (int c4 = 0; c4 < 32; c4++) {
                int c = chalf + c4 * 4;
                xs[(c + 0) * 132 + es] = 0.f;
                xs[(c + 1) * 132 + es] = 0.f;
                xs[(c + 2) * 132 + es] = 0.f;
                xs[(c + 3) * 132 + es] = 0.f;
            }
        }
        __syncthreads();

        unsigned long long acc[4][4];  // [channel][edge-pair]
        #pragma unroll
        for (int c = 0; c < 4; c++)
            #pragma unroll
            for (int p = 0; p < 4; p++) acc[c][p] = 0ull;

        const int xbase = eg * 8;
        #pragma unroll 2
        for (int k = 0; k < C1; k++) {
            float4 w = *(const float4*)(ws + k * C2 + c0);
            unsigned long long wd0 = pack2(w.x, w.x);
            unsigned long long wd1 = pack2(w.y, w.y);
            unsigned long long wd2 = pack2(w.z, w.z);
            unsigned long long wd3 = pack2(w.w, w.w);
            ulonglong2 xa = *(const ulonglong2*)(xs + k * 132 + xbase);
            ulonglong2 xb = *(const ulonglong2*)(xs + k * 132 + xbase + 4);
            fma2(acc[0][0], wd0, xa.x); fma2(acc[0][1], wd0, xa.y);
            fma2(acc[0][2], wd0, xb.x); fma2(acc[0][3], wd0, xb.y);
            fma2(acc[1][0], wd1, xa.x); fma2(acc[1][1], wd1, xa.y);
            fma2(acc[1][2], wd1, xb.x); fma2(acc[1][3], wd1, xb.y);
            fma2(acc[2][0], wd2, xa.x); fma2(acc[2][1], wd2, xa.y);
            fma2(acc[2][2], wd2, xb.x); fma2(acc[2][3], wd2, xb.y);
            fma2(acc[3][0], wd3, xa.x); fma2(acc[3][1], wd3, xa.y);
            fma2(acc[3][2], wd3, xb.x); fma2(acc[3][3], wd3, xb.y);
        }

        float vv[4][8];
        #pragma unroll
        for (int c = 0; c < 4; c++)
            #pragma unroll
            for (int p = 0; p < 4; p++) {
                float2 f = unpack2(acc[c][p]);
                vv[c][2 * p]     = f.x + bb[c];
                vv[c][2 * p + 1] = f.y + bb[c];
            }
        const int e0 = base + eg * 8;
        if (base + 128 <= E) {
            #pragma unroll
            for (int j = 0; j < 8; j++) {
                float4 v = make_float4(vv[0][j], vv[1][j], vv[2][j], vv[3][j]);
                *(float4*)&g_h2[(size_t)(e0 + j) * C2 + c0] = v;
            }
            #pragma unroll
            for (int c = 0; c < 4; c++)
                #pragma unroll
                for (int j = 0; j < 8; j++) {
                    lsum[c] += vv[c][j];
                    lssq[c] += vv[c][j] * vv[c][j];
                }
        } else {
            for (int j = 0; j < 8; j++) {
                int e = e0 + j;
                if (e < E) {
                    #pragma unroll
                    for (int c = 0; c < 4; c++) {
                        g_h2[(size_t)e * C2 + c0 + c] = vv[c][j];
                        lsum[c] += vv[c][j];
                        lssq[c] += vv[c][j] * vv[c][j];
                    }
                }
            }
        }
    }
    #pragma unroll
    for (int c = 0; c < 4; c++) {
        atomicAdd(&bsum2[c0 + c], lsum[c]);
        atomicAdd(&bssq2[c0 + c], lssq[c]);
    }
    __syncthreads();
    if (tid < C2) {
        atomicAdd(&g_sum2[tid], bsum2[tid]);
        atomicAdd(&g_ssq2[tid], bssq2[tid]);
    }
}

// ---------- K5: finalize layer-2 stats ----------
__global__ void k_fin2(float invE) {
    int c = threadIdx.x; // 64
    float m = g_sum2[c] * invE;
    float v = g_ssq2[c] * invE - m * m;
    g_mean2[c] = m;
    g_rstd2[c] = rsqrtf(v + 1e-5f);
}

// ---------- K6: norm+relu(h2) @ W3 + b3 -> out.  4 lanes per edge, shfl reduce ----------
__global__ void __launch_bounds__(256) k_out(
    const float* __restrict__ W3, const float* __restrict__ b3,
    float* __restrict__ out, int E)
{
    __shared__ float w3s[C2], m2s[C2], r2s[C2];
    const int tid = threadIdx.x;
    if (tid < C2) { w3s[tid] = W3[tid]; m2s[tid] = g_mean2[tid]; r2s[tid] = g_rstd2[tid]; }
    __syncthreads();
    const float b = b3[0];
    const int lane = tid & 31, wid = tid >> 5;
    const int q = lane & 3, el = lane >> 2;

    for (int base = blockIdx.x * 64; base < E; base += gridDim.x * 64) {
        int e = base + wid * 8 + el;
        float acc = 0.f;
        if (e < E) {
            const float4* rp = (const float4*)(g_h2 + (size_t)e * C2);
            #pragma unroll
            for (int t = 0; t < 4; t++) {
                float4 v = rp[q + 4 * t];
                int c = 16 * t + 4 * q;
                acc += fmaxf((v.x - m2s[c + 0]) * r2s[c + 0], 0.f) * w3s[c + 0];
                acc += fmaxf((v.y - m2s[c + 1]) * r2s[c + 1], 0.f) * w3s[c + 1];
                acc += fmaxf((v.z - m2s[c + 2]) * r2s[c + 2], 0.f) * w3s[c + 2];
                acc += fmaxf((v.w - m2s[c + 3]) * r2s[c + 3], 0.f) * w3s[c + 3];
            }
        }
        acc += __shfl_xor_sync(0xffffffffu, acc, 1);
        acc += __shfl_xor_sync(0xffffffffu, acc, 2);
        if (q == 0 && e < E) out[e] = acc + b;
    }
}

// ---------- launch ----------
extern "C" void kernel_launch(void* const* d_in, const int* in_sizes, int n_in,
                              void* d_out, int out_size) {
    const float* emb  = (const float*)d_in[0];
    const void*  eidx = d_in[1];
    const float* W1   = (const float*)d_in[2];
    const float* b1   = (const float*)d_in[3];
    const float* W2   = (const float*)d_in[4];
    const float* b2   = (const float*)d_in[5];
    const float* W3   = (const float*)d_in[6];
    const float* b3   = (const float*)d_in[7];
    float*       out  = (float*)d_out;

    const int N = in_sizes[0] / HDIM;
    const int E = in_sizes[1] / 2;
    if (E <= 0 || N <= 0 || N > NMAX || E > EMAXN) return;
    const float invE = 1.0f / (float)E;

    cudaFuncSetAttribute(k_pre,    cudaFuncAttributeMaxDynamicSharedMemorySize, SMEMP_BYTES);
    cudaFuncSetAttribute(k_gemm2f, cudaFuncAttributeMaxDynamicSharedMemorySize, SMEM2_BYTES);

    k_sniff<<<1, 32>>>(eidx, E, N);
    int cb = (E + 255) / 256; if (cb > 1216) cb = 1216;
    k_cvt<<<cb, 256>>>(eidx, E);
    k_zero_stats<<<1, 256>>>();
    k_pre<<<152, 256, SMEMP_BYTES>>>(emb, W1, N);
    k_stats1<<<1216, 256>>>(b1, E);
    k_fin1<<<1, C1>>>(invE);
    k_fold<<<608, 256>>>(b1, N);
    k_gemm2f<<<152, 256, SMEM2_BYTES>>>(W2, b2, E);
    k_fin2<<<1, C2>>>(invE);
    int nb = (E + 63) / 64;
    if (nb > 4864) nb = 4864;
    k_out<<<nb, 256>>>(W3, b3, out, E);
}